// round 1
// baseline (speedup 1.0000x reference)
#include <cuda_runtime.h>

#define M_MOL 64
#define NA    24
#define P     276
#define T_ROWS 6000
#define TT    48
#define NBLK  (T_ROWS/TT)      // 125
#define NTHR  384
#define QC    0.22360679774997896f   // sqrt(5)/sig, sig=10
#define C0    0.0166666666666667f    // 5/(3*sig^2) = 1/60

// ---------------- scratch (__device__ globals: no allocations allowed) ----
__device__ float g_qxsT[P * M_MOL];     // [p][m]  q * xs
__device__ float g_xs3 [M_MOL * P];     // [m][p]  xs^3
__device__ float g_nrm [M_MOL];         // |q xs_m|^2
__device__ float g_tn  [T_ROWS];        // |q xst_t|^2
__device__ float g_tc  [T_ROWS];        // q xst_t . Jx_t
__device__ float g_Apart [NBLK * M_MOL * P];
__device__ float g_S1part[NBLK * M_MOL];
__device__ float g_Espart[NBLK * M_MOL];

// ---------------- kernel 1a: per-molecule descriptors ---------------------
__global__ void k_prep_m(const float* __restrict__ Rs) {
    int m = blockIdx.x;
    int p = threadIdx.x;
    __shared__ float s_nrm;
    if (p == 0) s_nrm = 0.0f;
    __syncthreads();
    if (p < P) {
        // pair (i,j), i>j, p = i*(i-1)/2 + j  (tril_indices order)
        int i = 1;
        while (i * (i + 1) / 2 <= p) i++;
        int j = p - i * (i - 1) / 2;
        const float* a = Rs + (m * NA + i) * 3;
        const float* b = Rs + (m * NA + j) * 3;
        float dx = a[0] - b[0], dy = a[1] - b[1], dz = a[2] - b[2];
        float r2 = dx * dx + dy * dy + dz * dz;
        float xs = rsqrtf(r2);              // 1/dist
        float qxs = QC * xs;
        g_qxsT[p * M_MOL + m] = qxs;
        g_xs3[m * P + p] = xs * xs * xs;
        atomicAdd(&s_nrm, qxs * qxs);
    }
    __syncthreads();
    if (p == 0) g_nrm[m] = s_nrm;
}

// ---------------- kernel 1b: per-training-point stats ---------------------
__global__ void k_prep_t(const float* __restrict__ xst, const float* __restrict__ Jx) {
    int warp = (blockIdx.x * blockDim.x + threadIdx.x) >> 5;
    int lane = threadIdx.x & 31;
    if (warp >= T_ROWS) return;
    const float* xr = xst + warp * P;
    const float* jr = Jx + warp * P;
    float tn = 0.0f, tc = 0.0f;
    for (int p = lane; p < P; p += 32) {
        float x = QC * xr[p];
        float j = jr[p];
        tn = fmaf(x, x, tn);
        tc = fmaf(x, j, tc);
    }
    #pragma unroll
    for (int o = 16; o; o >>= 1) {
        tn += __shfl_down_sync(0xffffffffu, tn, o);
        tc += __shfl_down_sync(0xffffffffu, tc, o);
    }
    if (lane == 0) { g_tn[warp] = tn; g_tc[warp] = tc; }
}

// ---------------- kernel 2: main fused dual-GEMM --------------------------
// smem layout (floats):
//  sX  : [P][50]   q*xs_train tile, p-major      @ 0        (13800)
//  sJ  : [P][50]   Jx tile, p-major              @ 13800    (13800)
//  sQx : [P][M]    qxs transposed                @ 27600    (17664)
//  sW1 : [TT][M]                                 @ 45264    (3072)
//  sW2 : [TT][M]                                 @ 48336    (3072)
//  sDot: [TT][M]                                 @ 51408    (3072)
//  sTn : [TT]                                    @ 54480
//  sTc : [TT]                                    @ 54528
//  sNrm: [M]                                     @ 54576  -> total 54640 fl = 218560 B
#define SMEM_FLOATS 54640
#define SMEM_BYTES  (SMEM_FLOATS * 4)
#define TSTRIDE 50

__global__ __launch_bounds__(NTHR, 1)
void k_main(const float* __restrict__ xst, const float* __restrict__ Jx) {
    extern __shared__ float sm[];
    float* sX   = sm;
    float* sJ   = sm + 13800;
    float* sQx  = sm + 27600;
    float* sW1  = sm + 45264;
    float* sW2  = sm + 48336;
    float* sDot = sm + 51408;
    float* sTn  = sm + 54480;
    float* sTc  = sm + 54528;
    float* sNrm = sm + 54576;

    const int tid = threadIdx.x;
    const int blk = blockIdx.x;
    const int t0  = blk * TT;

    // ---- stage qxs^T (vectorized) ----
    {
        const float4* src4 = (const float4*)g_qxsT;
        float4* dst4 = (float4*)sQx;
        #pragma unroll 4
        for (int i = tid; i < P * M_MOL / 4; i += NTHR) dst4[i] = src4[i];
    }
    // ---- stage train tile transposed (p-major) ----
    for (int idx = tid; idx < TT * P; idx += NTHR) {
        int t = idx / P;
        int p = idx - t * P;
        sX[p * TSTRIDE + t] = QC * xst[(t0 + t) * P + p];
        sJ[p * TSTRIDE + t] = Jx[(t0 + t) * P + p];
    }
    if (tid < TT) { sTn[tid] = g_tn[t0 + tid]; sTc[tid] = g_tc[t0 + tid]; }
    else if (tid >= 64 && tid < 128) sNrm[tid - 64] = g_nrm[tid - 64];
    __syncthreads();

    // ---- phase A: G1 = qxs.qxst^T, G2 = qxs.Jx^T  (64 x 48 dual GEMM) ----
    const int ty = tid & 15;        // m group (4 m's)
    const int tx = tid >> 4;        // t group (2 t's), 0..23
    const int m4 = ty * 4;
    const int t2 = tx * 2;

    float g1[4][2] = {}, g2[4][2] = {};
    #pragma unroll 4
    for (int p = 0; p < P; p++) {
        float4 a = *(const float4*)&sQx[p * M_MOL + m4];
        float2 b = *(const float2*)&sX[p * TSTRIDE + t2];
        float2 c = *(const float2*)&sJ[p * TSTRIDE + t2];
        float av[4] = {a.x, a.y, a.z, a.w};
        float bv[2] = {b.x, b.y};
        float cv[2] = {c.x, c.y};
        #pragma unroll
        for (int i2 = 0; i2 < 4; i2++)
            #pragma unroll
            for (int j2 = 0; j2 < 2; j2++) {
                g1[i2][j2] = fmaf(av[i2], bv[j2], g1[i2][j2]);
                g2[i2][j2] = fmaf(av[i2], cv[j2], g2[i2][j2]);
            }
    }

    // ---- weights w1/w2/dot ----
    #pragma unroll
    for (int j2 = 0; j2 < 2; j2++) {
        int t = t2 + j2;
        float tn = sTn[t], tc = sTc[t];
        #pragma unroll
        for (int i2 = 0; i2 < 4; i2++) {
            int m = m4 + i2;
            float d2   = fmaf(-2.0f, g1[i2][j2], sNrm[m] + tn);
            float dist = sqrtf(fmaxf(d2, 0.0f));
            float e    = C0 * __expf(-dist);
            float dot  = g2[i2][j2] - tc;
            sW1[t * M_MOL + m]  = e * dot;
            sW2[t * M_MOL + m]  = fmaf(e, dist, e);   // e*(1+dist)
            sDot[t * M_MOL + m] = dot;
        }
    }
    __syncthreads();

    // ---- per-m scalars S1, Es partials ----
    if (tid < M_MOL) {
        float s1 = 0.0f, es = 0.0f;
        #pragma unroll 8
        for (int t = 0; t < TT; t++) {
            s1 += sW1[t * M_MOL + tid];
            es = fmaf(sW2[t * M_MOL + tid], sDot[t * M_MOL + tid], es);
        }
        g_S1part[blk * M_MOL + tid] = s1;
        g_Espart[blk * M_MOL + tid] = es;
    }

    // ---- phase B: A[m,p] = sum_t (w1*qxst + w2*Jx)  (64 x 276 GEMM) ----
    const int pg = tid >> 4;            // 0..23, p = pg + 24*i
    const bool has12 = (pg < 12);       // i==11 -> p = 264+pg < 276
    float acc[4][12];
    #pragma unroll
    for (int mi = 0; mi < 4; mi++)
        #pragma unroll
        for (int i = 0; i < 12; i++) acc[mi][i] = 0.0f;

    for (int t = 0; t < TT; t++) {
        float4 w1 = *(const float4*)&sW1[t * M_MOL + m4];
        float4 w2 = *(const float4*)&sW2[t * M_MOL + m4];
        float w1v[4] = {w1.x, w1.y, w1.z, w1.w};
        float w2v[4] = {w2.x, w2.y, w2.z, w2.w};
        #pragma unroll
        for (int i = 0; i < 11; i++) {
            int p = pg + 24 * i;
            float x = sX[p * TSTRIDE + t];
            float j = sJ[p * TSTRIDE + t];
            #pragma unroll
            for (int mi = 0; mi < 4; mi++)
                acc[mi][i] = fmaf(w1v[mi], x, fmaf(w2v[mi], j, acc[mi][i]));
        }
        if (has12) {
            int p = pg + 264;
            float x = sX[p * TSTRIDE + t];
            float j = sJ[p * TSTRIDE + t];
            #pragma unroll
            for (int mi = 0; mi < 4; mi++)
                acc[mi][11] = fmaf(w1v[mi], x, fmaf(w2v[mi], j, acc[mi][11]));
        }
    }
    __syncthreads();

    // ---- stage to smem then coalesced global write ----
    float* sAcc = sm;   // reuse sX+sJ region (17664 < 27600 floats)
    #pragma unroll
    for (int i = 0; i < 12; i++) {
        int p = pg + 24 * i;
        if (i < 11 || has12) {
            #pragma unroll
            for (int mi = 0; mi < 4; mi++)
                sAcc[(m4 + mi) * P + p] = acc[mi][i];
        }
    }
    __syncthreads();
    float* gA = g_Apart + blk * M_MOL * P;
    #pragma unroll 4
    for (int idx = tid; idx < M_MOL * P; idx += NTHR) gA[idx] = sAcc[idx];
}

// ---------------- kernel 3: reduce partials, build Fs and Es --------------
__global__ void k_final(const float* __restrict__ Rs, float* __restrict__ out) {
    int m = blockIdx.x;
    int tid = threadIdx.x;            // 288 threads
    __shared__ float sFsx[P];
    __shared__ float sS1, sEs;

    if (tid < 32) {
        float s1 = 0.0f, es = 0.0f;
        for (int b = tid; b < NBLK; b += 32) {
            s1 += g_S1part[b * M_MOL + m];
            es += g_Espart[b * M_MOL + m];
        }
        #pragma unroll
        for (int o = 16; o; o >>= 1) {
            s1 += __shfl_down_sync(0xffffffffu, s1, o);
            es += __shfl_down_sync(0xffffffffu, es, o);
        }
        if (tid == 0) { sS1 = s1; sEs = es; }
    }
    __syncthreads();

    if (tid < P) {
        float a = 0.0f;
        for (int b = 0; b < NBLK; b++) a += g_Apart[(b * M_MOL + m) * P + tid];
        sFsx[tid] = (g_qxsT[tid * M_MOL + m] * sS1 - a) * g_xs3[m * P + tid];
    }
    __syncthreads();

    if (tid < NA * 3) {
        int atom = tid / 3, d = tid % 3;
        float ra = Rs[(m * NA + atom) * 3 + d];
        float f = 0.0f;
        #pragma unroll
        for (int b = 0; b < NA; b++) {
            if (b == atom) continue;
            int hi = (atom > b) ? atom : b;
            int lo = (atom > b) ? b : atom;
            int pi = hi * (hi - 1) / 2 + lo;
            f = fmaf(Rs[(m * NA + b) * 3 + d] - ra, sFsx[pi], f);
        }
        out[M_MOL + (m * NA + atom) * 3 + d] = f;   // Fs after Es block
    }
    if (tid == 0) out[m] = sEs * (1.0f / QC);       // Es = sum(exp1*dot)/q
}

// ---------------- entry ---------------------------------------------------
extern "C" void kernel_launch(void* const* d_in, const int* in_sizes, int n_in,
                              void* d_out, int out_size) {
    const float* Rs  = (const float*)d_in[0];
    const float* xst = (const float*)d_in[1];
    const float* Jx  = (const float*)d_in[2];
    float* out = (float*)d_out;

    cudaFuncSetAttribute(k_main, cudaFuncAttributeMaxDynamicSharedMemorySize, SMEM_BYTES);

    k_prep_m<<<M_MOL, 288>>>(Rs);
    k_prep_t<<<T_ROWS / 8, 256>>>(xst, Jx);
    k_main<<<NBLK, NTHR, SMEM_BYTES>>>(xst, Jx);
    k_final<<<M_MOL, 288>>>(Rs, out);
}